// round 12
// baseline (speedup 1.0000x reference)
#include <cuda_runtime.h>
#include <cstdint>

#define B_ 1024
#define T_ 256
#define D_ 64
#define H_ 128

// Precomputed x-projections (pre-activation, bias included).
__device__ float g_xg[(size_t)B_ * T_ * 256];   // gate: r cols 0..127, u cols 128..255
__device__ float g_xc[(size_t)B_ * T_ * 128];   // candidate
__device__ int   g_perm[B_];                    // rows sorted by len desc

// ---- packed f32x2 helpers ----
__device__ __forceinline__ unsigned long long pack2(float lo, float hi) {
    unsigned long long r;
    asm("mov.b64 %0, {%1, %2};" : "=l"(r) : "f"(lo), "f"(hi));
    return r;
}
__device__ __forceinline__ void fma2(unsigned long long& acc,
                                     unsigned long long a,
                                     unsigned long long b) {
    asm("fma.rn.f32x2 %0, %1, %2, %0;" : "+l"(acc) : "l"(a), "l"(b));
}
__device__ __forceinline__ float sum2(unsigned long long a) {
    float lo, hi;
    asm("mov.b64 {%0, %1}, %2;" : "=f"(lo), "=f"(hi) : "l"(a));
    return lo + hi;
}
__device__ __forceinline__ float sigmoidf(float s) { return 1.f / (1.f + __expf(-s)); }
__device__ __forceinline__ float tanh_safe(float s) {
    const float sc = fminf(fmaxf(s, -15.f), 15.f);
    const float e  = __expf(2.f * sc);
    return (e - 1.f) / (e + 1.f);
}

// ============================================================================
// Sort rows by seq_len descending (counting sort, one CTA).
// ============================================================================
__global__ void sort_rows(const int* __restrict__ seq_lens) {
    __shared__ int base[T_ + 1];
    const int tid = threadIdx.x;          // 1024 threads
    if (tid <= T_) base[tid] = 0;
    __syncthreads();
    const int len = seq_lens[tid];
    atomicAdd(&base[len], 1);
    __syncthreads();
    if (tid == 0) {                        // descending prefix
        int acc = 0;
        for (int l = T_; l >= 0; l--) { int c = base[l]; base[l] = acc; acc += c; }
    }
    __syncthreads();
    const int pos = atomicAdd(&base[len], 1);
    g_perm[pos] = tid;
}

// ============================================================================
// Phase A: time-parallel x-projections. Weights in regs, x via LDS.128.
// ============================================================================
__global__ __launch_bounds__(384)
void gru_phaseA(const int* __restrict__ item_his,
                const int* __restrict__ seq_lens,
                const float* __restrict__ emb,
                const float* __restrict__ Wg,
                const float* __restrict__ bg,
                const float* __restrict__ Wc,
                const float* __restrict__ bc)
{
    const int b  = blockIdx.y;
    const int t0 = blockIdx.x * 64;
    const int len = seq_lens[b];
    if (t0 >= len) return;
    const int nt = min(64, len - t0);
    const int tid = threadIdx.x;

    __shared__ int idx_sh[64];
    __shared__ __align__(16) float x_sh[64 * 64];

    unsigned long long wp[32];
    float bias;
    if (tid < 256) {
        bias = bg[tid];
#pragma unroll
        for (int i = 0; i < 32; i++)
            wp[i] = pack2(Wg[(2 * i) * 256 + tid], Wg[(2 * i + 1) * 256 + tid]);
    } else {
        const int c = tid - 256;
        bias = bc[c];
#pragma unroll
        for (int i = 0; i < 32; i++)
            wp[i] = pack2(Wc[(2 * i) * 128 + c], Wc[(2 * i + 1) * 128 + c]);
    }

    if (tid < nt) idx_sh[tid] = item_his[b * T_ + t0 + tid];
    __syncthreads();

    {   // coalesced gather: nt embedding rows of 256B each
        const float4* e4 = (const float4*)emb;
        float4* x4 = (float4*)x_sh;
        for (int i = tid; i < nt * 16; i += 384) {
            const int r = i >> 4, q = i & 15;
            x4[r * 16 + q] = e4[(size_t)idx_sh[r] * 16 + q];
        }
    }
    __syncthreads();

    const ulonglong2* x2 = (const ulonglong2*)x_sh;
    for (int r = 0; r < nt; r += 2) {
        const bool two = (r + 1 < nt);
        unsigned long long a0 = 0ULL, a1 = 0ULL, b0 = 0ULL, b1 = 0ULL;
#pragma unroll
        for (int i = 0; i < 16; i++) {
            ulonglong2 xx = x2[r * 16 + i];
            fma2(a0, xx.x, wp[2 * i]);
            fma2(a1, xx.y, wp[2 * i + 1]);
            if (two) {
                ulonglong2 yy = x2[(r + 1) * 16 + i];
                fma2(b0, yy.x, wp[2 * i]);
                fma2(b1, yy.y, wp[2 * i + 1]);
            }
        }
        const float acc0 = sum2(a0) + sum2(a1) + bias;
        const size_t p0 = (size_t)b * T_ + t0 + r;
        if (tid < 256) __stcs(&g_xg[p0 * 256 + tid], acc0);
        else           __stcs(&g_xc[p0 * 128 + (tid - 256)], acc0);
        if (two) {
            const float acc1 = sum2(b0) + sum2(b1) + bias;
            if (tid < 256) __stcs(&g_xg[(p0 + 1) * 256 + tid], acc1);
            else           __stcs(&g_xc[(p0 + 1) * 128 + (tid - 256)], acc1);
        }
    }
}

// ============================================================================
// Phase B: one CTA per batch row, 128 threads, 2 CTAs/SM.
//   Thread j holds weight columns r_j, u_j (Wg) and c_j (Wc) in registers
//   (96 packed b64). r/u dots share one h LDS.128 stream (1 LDS : 4 FMA2).
//   Two __syncthreads per step. CTAs launched in len-desc order (LPT).
// ============================================================================
__global__ __launch_bounds__(128, 2)
void gru_phaseB(const int* __restrict__ seq_lens,
                const float* __restrict__ Wg,
                const float* __restrict__ Wc,
                float* __restrict__ out)
{
    __shared__ __align__(16) float h[128];
    __shared__ __align__(16) float rh[128];

    const int j   = threadIdx.x;
    const int b   = g_perm[blockIdx.x];
    const int len = seq_lens[b];

    h[j] = 0.f;

    if (len > 0) {
        // register-resident weight columns (recurrent rows 64..191)
        unsigned long long wr[32], wu[32], wc[32];
#pragma unroll
        for (int i = 0; i < 32; i++) {
            const int k = 64 + 2 * i;
            wr[i] = pack2(Wg[k * 256 + j],       Wg[(k + 1) * 256 + j]);
            wu[i] = pack2(Wg[k * 256 + 128 + j], Wg[(k + 1) * 256 + 128 + j]);
            wc[i] = pack2(Wc[k * 128 + j],       Wc[(k + 1) * 128 + j]);
        }
        // second k-half
        unsigned long long wr2[32], wu2[32], wc2[32];
        // NOTE: 128 k-values = 64 pairs; split into two banks of 32 to keep
        // indexing trivially affine for ptxas.
#pragma unroll
        for (int i = 0; i < 32; i++) {
            const int k = 128 + 2 * i;
            wr2[i] = pack2(Wg[k * 256 + j],       Wg[(k + 1) * 256 + j]);
            wu2[i] = pack2(Wg[k * 256 + 128 + j], Wg[(k + 1) * 256 + 128 + j]);
            wc2[i] = pack2(Wc[k * 128 + j],       Wc[(k + 1) * 128 + j]);
        }

        int offg = b * (T_ * 256) + j;      // xg (r at +0, u at +128)
        int offc = b * (T_ * 128) + j;      // xc

        float qr = __ldcs(&g_xg[offg]);
        float qu = __ldcs(&g_xg[offg + 128]);
        float qc = __ldcs(&g_xc[offc]);

        __syncthreads();

        for (int t = 0; t < len; t++) {
            // prefetch next step's x-projections
            float nr = 0.f, nu = 0.f, nc = 0.f;
            if (t + 1 < len) {
                nr = __ldcs(&g_xg[offg + 256]);
                nu = __ldcs(&g_xg[offg + 256 + 128]);
                nc = __ldcs(&g_xc[offc + 128]);
            }

            // ---- r,u dots: shared h stream ----
            const ulonglong2* hp = (const ulonglong2*)h;
            unsigned long long r0 = 0ULL, r1 = 0ULL, u0 = 0ULL, u1 = 0ULL;
#pragma unroll
            for (int i = 0; i < 16; i++) {
                ulonglong2 hv = hp[i];                 // LDS.128 broadcast
                fma2(r0, hv.x, wr[2 * i]);
                fma2(r1, hv.y, wr[2 * i + 1]);
                fma2(u0, hv.x, wu[2 * i]);
                fma2(u1, hv.y, wu[2 * i + 1]);
            }
#pragma unroll
            for (int i = 0; i < 16; i++) {
                ulonglong2 hv = hp[16 + i];
                fma2(r0, hv.x, wr2[2 * i]);
                fma2(r1, hv.y, wr2[2 * i + 1]);
                fma2(u0, hv.x, wu2[2 * i]);
                fma2(u1, hv.y, wu2[2 * i + 1]);
            }
            const float hj = h[j];
            const float r  = sigmoidf(sum2(r0) + sum2(r1) + qr);
            const float u  = sigmoidf(sum2(u0) + sum2(u1) + qu);
            rh[j] = r * hj;
            __syncthreads();

            // ---- candidate dot over rh ----
            const ulonglong2* rp = (const ulonglong2*)rh;
            unsigned long long c0 = 0ULL, c1 = 0ULL;
#pragma unroll
            for (int i = 0; i < 16; i++) {
                ulonglong2 rv = rp[i];
                fma2(c0, rv.x, wc[2 * i]);
                fma2(c1, rv.y, wc[2 * i + 1]);
            }
#pragma unroll
            for (int i = 0; i < 16; i++) {
                ulonglong2 rv = rp[16 + i];
                fma2(c0, rv.x, wc2[2 * i]);
                fma2(c1, rv.y, wc2[2 * i + 1]);
            }
            const float c = tanh_safe(sum2(c0) + sum2(c1) + qc);
            h[j] = u * hj + (1.f - u) * c;
            __syncthreads();

            qr = nr; qu = nu; qc = nc;
            offg += 256; offc += 128;
        }
    }

    out[b * H_ + j] = h[j];
}

// ============================================================================
extern "C" void kernel_launch(void* const* d_in, const int* in_sizes, int n_in,
                              void* d_out, int out_size)
{
    const int*   item_his = (const int*)d_in[0];
    const int*   seq_lens = (const int*)d_in[1];
    const float* emb      = (const float*)d_in[2];
    const float* Wg       = (const float*)d_in[3];
    const float* bg       = (const float*)d_in[4];
    const float* Wc       = (const float*)d_in[5];
    const float* bc       = (const float*)d_in[6];
    float* out = (float*)d_out;

    sort_rows<<<1, B_>>>(seq_lens);
    dim3 gA(T_ / 64, B_);   // (4, 1024)
    gru_phaseA<<<gA, 384>>>(item_his, seq_lens, emb, Wg, bg, Wc, bc);
    gru_phaseB<<<B_, 128>>>(seq_lens, Wg, Wc, out);
}